// round 4
// baseline (speedup 1.0000x reference)
#include <cuda_runtime.h>
#include <cuda_bf16.h>
#include <cstdint>

// Problem constants
#define BB 4
#define TT 2048
#define EE 1024
#define HH 16
#define DD 64
#define MM (BB*TT)          // 8192

// ---------------- scratch (device globals; no runtime alloc allowed) ------
__device__ float g_qp[MM * EE];
__device__ float g_kp[MM * EE];
__device__ float g_vp[MM * EE];
__device__ float g_y [MM * EE];

// ---------------- helpers -------------------------------------------------
__device__ __forceinline__ uint32_t f2tf32(float x) {
    uint32_t r;
    asm("cvt.rna.tf32.f32 %0, %1;" : "=r"(r) : "f"(x));
    return r;
}

// 3xTF32 split: x ~= hi + lo with both representable in tf32
__device__ __forceinline__ void split32(float x, uint32_t& hi, uint32_t& lo) {
    hi = f2tf32(x);
    lo = f2tf32(x - __uint_as_float(hi));
}

__device__ __forceinline__ void mma_tf32(float* c, const uint32_t* a, const uint32_t* b) {
    asm volatile(
        "mma.sync.aligned.m16n8k8.row.col.f32.tf32.tf32.f32 "
        "{%0,%1,%2,%3}, {%4,%5,%6,%7}, {%8,%9}, {%0,%1,%2,%3};\n"
        : "+f"(c[0]), "+f"(c[1]), "+f"(c[2]), "+f"(c[3])
        : "r"(a[0]), "r"(a[1]), "r"(a[2]), "r"(a[3]), "r"(b[0]), "r"(b[1]));
}

__device__ __forceinline__ void cp16(void* smem_dst, const void* gsrc) {
    unsigned d = (unsigned)__cvta_generic_to_shared(smem_dst);
    asm volatile("cp.async.cg.shared.global [%0], [%1], 16;\n" :: "r"(d), "l"(gsrc));
}

// =====================================================================
// GEMM: C[M,N] = A[M,K] @ W[N,K]^T (+ bias), 3xTF32 mma, 128x128x32 tiles
// =====================================================================
#define GBM 128
#define GBN 128
#define GBK 32
#define GPAD 36   // row stride (floats): 4g+tig bank pattern -> conflict free
#define GEMM_SMEM (2 * (GBM + GBN) * GPAD * 4)   // 73728 bytes

__global__ void __launch_bounds__(256)
gemm_tn_kernel(const float* __restrict__ A,
               const float* __restrict__ W,
               const float* __restrict__ bias,
               float* __restrict__ C,
               int M, int N, int K)
{
    extern __shared__ float smem[];
    float* sA = smem;                       // 2 stages * GBM * GPAD
    float* sB = smem + 2 * GBM * GPAD;      // 2 stages * GBN * GPAD

    const int t  = threadIdx.x;
    const int m0 = blockIdx.y * GBM;
    const int n0 = blockIdx.x * GBN;

    const int warp = t >> 5;
    const int lane = t & 31;
    const int g    = lane >> 2;
    const int tig  = lane & 3;
    const int wm   = (warp & 1) * 64;       // warp tile 64x32, warps 2(m) x 4(n)
    const int wn   = (warp >> 1) * 32;

    const int lr = t >> 3;                  // 0..31
    const int lc = (t & 7) << 2;            // 0,4,..,28

    auto stage_load = [&](int s, int k0) {
        float* dA = sA + s * GBM * GPAD;
        float* dB = sB + s * GBN * GPAD;
#pragma unroll
        for (int p = 0; p < 4; ++p) {
            int row = lr + p * 32;
            cp16(dA + row * GPAD + lc, A + (size_t)(m0 + row) * K + k0 + lc);
            cp16(dB + row * GPAD + lc, W + (size_t)(n0 + row) * K + k0 + lc);
        }
        asm volatile("cp.async.commit_group;\n");
    };

    float acc[4][4][4];
#pragma unroll
    for (int mt = 0; mt < 4; ++mt)
#pragma unroll
        for (int nt = 0; nt < 4; ++nt)
#pragma unroll
            for (int r = 0; r < 4; ++r) acc[mt][nt][r] = 0.f;

    const int KT = K / GBK;
    stage_load(0, 0);
    stage_load(1, GBK);

    for (int kt = 0; kt < KT; ++kt) {
        const int s = kt & 1;
        asm volatile("cp.async.wait_group 1;\n");
        __syncthreads();
        const float* cA = sA + s * GBM * GPAD;
        const float* cB = sB + s * GBN * GPAD;
#pragma unroll
        for (int ks = 0; ks < 4; ++ks) {
            const int kk = ks * 8;
            uint32_t ah[4][4], al[4][4], bh[4][2], bl[4][2];
#pragma unroll
            for (int mt = 0; mt < 4; ++mt) {
                const float* base = cA + (wm + mt * 16 + g) * GPAD + kk + tig;
                split32(base[0],            ah[mt][0], al[mt][0]);
                split32(base[4],            ah[mt][2], al[mt][2]);
                split32(base[8 * GPAD],     ah[mt][1], al[mt][1]);
                split32(base[8 * GPAD + 4], ah[mt][3], al[mt][3]);
            }
#pragma unroll
            for (int nt = 0; nt < 4; ++nt) {
                const float* base = cB + (wn + nt * 8 + g) * GPAD + kk + tig;
                split32(base[0], bh[nt][0], bl[nt][0]);
                split32(base[4], bh[nt][1], bl[nt][1]);
            }
#pragma unroll
            for (int mt = 0; mt < 4; ++mt)
#pragma unroll
                for (int nt = 0; nt < 4; ++nt) {
                    mma_tf32(acc[mt][nt], ah[mt], bh[nt]);   // hi*hi
                    mma_tf32(acc[mt][nt], al[mt], bh[nt]);   // lo*hi
                    mma_tf32(acc[mt][nt], ah[mt], bl[nt]);   // hi*lo
                }
        }
        __syncthreads();
        if (kt + 2 < KT) stage_load(s, (kt + 2) * GBK);
        else asm volatile("cp.async.commit_group;\n");
    }

    // epilogue
#pragma unroll
    for (int mt = 0; mt < 4; ++mt) {
        const int r0 = m0 + wm + mt * 16 + g;
#pragma unroll
        for (int nt = 0; nt < 4; ++nt) {
            const int c = n0 + wn + nt * 8 + 2 * tig;
            float b0 = bias ? bias[c]     : 0.f;
            float b1 = bias ? bias[c + 1] : 0.f;
            C[(size_t)r0 * N + c]           = acc[mt][nt][0] + b0;
            C[(size_t)r0 * N + c + 1]       = acc[mt][nt][1] + b1;
            C[(size_t)(r0 + 8) * N + c]     = acc[mt][nt][2] + b0;
            C[(size_t)(r0 + 8) * N + c + 1] = acc[mt][nt][3] + b1;
        }
    }
}

// =====================================================================
// Flash attention (causal), per-(b,h) head, 64-row Q tiles, 64-key steps
// scale = +sqrt(D) = 8 (faithful reference quirk), 3xTF32 throughout
// =====================================================================
#define APAD 68
#define ATTN_SMEM (3 * 64 * APAD * 4)   // 52224 bytes: sK, sVT, sPQ

__global__ void __launch_bounds__(128)
attn_kernel(const float* __restrict__ qp,
            const float* __restrict__ kp,
            const float* __restrict__ vp,
            float* __restrict__ y)
{
    extern __shared__ float smem[];
    float* sK  = smem;                  // [key][d]   64 x APAD
    float* sVT = smem + 64 * APAD;      // [d][key]   64 x APAD
    float* sPQ = smem + 2 * 64 * APAD;  // Q then P   [row][col] 64 x APAD

    const int qi = blockIdx.x;          // q tile 0..31
    const int bh = blockIdx.y;          // 0..63
    const int b  = bh >> 4;
    const int h  = bh & 15;
    const int t  = threadIdx.x;
    const int warp = t >> 5, lane = t & 31;
    const int g = lane >> 2, tig = lane & 3;
    const int wq = warp * 16;

    const size_t qbase = ((size_t)b * TT + (size_t)qi * 64) * EE + h * DD;

    // ---- load Q tile ----
    {
        const int r  = t >> 1;
        const int c0 = (t & 1) * 32;
        const float* src = qp + qbase + (size_t)r * EE + c0;
        float* dst = sPQ + r * APAD + c0;
#pragma unroll
        for (int i = 0; i < 8; ++i)
            ((float4*)dst)[i] = ((const float4*)src)[i];
    }
    __syncthreads();

    // ---- Q fragments (hi/lo), register-resident for the whole kernel ----
    uint32_t qh[8][4], ql[8][4];
#pragma unroll
    for (int kt = 0; kt < 8; ++kt) {
        const float* base = sPQ + (wq + g) * APAD + kt * 8 + tig;
        split32(base[0],            qh[kt][0], ql[kt][0]);
        split32(base[4],            qh[kt][2], ql[kt][2]);
        split32(base[8 * APAD],     qh[kt][1], ql[kt][1]);
        split32(base[8 * APAD + 4], qh[kt][3], ql[kt][3]);
    }

    float m_r[2] = {-INFINITY, -INFINITY};
    float l_r[2] = {0.f, 0.f};
    float yacc[8][4];
#pragma unroll
    for (int nt = 0; nt < 8; ++nt)
#pragma unroll
        for (int r = 0; r < 4; ++r) yacc[nt][r] = 0.f;

    for (int j = 0; j <= qi; ++j) {
        __syncthreads();   // previous iteration done with sK / sVT

        // ---- load K tile [key][d] and V transposed [d][key] ----
        {
            const int r  = t >> 1;
            const int c0 = (t & 1) * 32;
            const size_t kb = ((size_t)b * TT + (size_t)j * 64) * EE + h * DD;
            const float* srcK = kp + kb + (size_t)r * EE + c0;
            float* dstK = sK + r * APAD + c0;
#pragma unroll
            for (int i = 0; i < 8; ++i)
                ((float4*)dstK)[i] = ((const float4*)srcK)[i];
            const float* srcV = vp + kb + (size_t)r * EE + c0;
#pragma unroll
            for (int i = 0; i < 8; ++i) {
                float4 vv = ((const float4*)srcV)[i];
                const int c = c0 + i * 4;
                sVT[(c + 0) * APAD + r] = vv.x;
                sVT[(c + 1) * APAD + r] = vv.y;
                sVT[(c + 2) * APAD + r] = vv.z;
                sVT[(c + 3) * APAD + r] = vv.w;
            }
        }
        __syncthreads();

        // ---- S = Q K^T (16x64 per warp), 3xTF32 ----
        float s[8][4];
#pragma unroll
        for (int nt = 0; nt < 8; ++nt)
#pragma unroll
            for (int r = 0; r < 4; ++r) s[nt][r] = 0.f;
#pragma unroll
        for (int kt = 0; kt < 8; ++kt) {
            uint32_t kh[8][2], kl[8][2];
#pragma unroll
            for (int nt = 0; nt < 8; ++nt) {
                const float* base = sK + (nt * 8 + g) * APAD + kt * 8 + tig;
                split32(base[0], kh[nt][0], kl[nt][0]);
                split32(base[4], kh[nt][1], kl[nt][1]);
            }
#pragma unroll
            for (int nt = 0; nt < 8; ++nt) {
                mma_tf32(s[nt], qh[kt], kh[nt]);
                mma_tf32(s[nt], ql[kt], kh[nt]);
                mma_tf32(s[nt], qh[kt], kl[nt]);
            }
        }

        // ---- scale (+mask on diagonal tile) ----
        const float scale = 8.0f;
        if (j == qi) {
            const int r0 = wq + g, r1 = wq + g + 8;
#pragma unroll
            for (int nt = 0; nt < 8; ++nt) {
                const int c = nt * 8 + 2 * tig;
                s[nt][0] = (c     <= r0) ? s[nt][0] * scale : -INFINITY;
                s[nt][1] = (c + 1 <= r0) ? s[nt][1] * scale : -INFINITY;
                s[nt][2] = (c     <= r1) ? s[nt][2] * scale : -INFINITY;
                s[nt][3] = (c + 1 <= r1) ? s[nt][3] * scale : -INFINITY;
            }
        } else {
#pragma unroll
            for (int nt = 0; nt < 8; ++nt)
#pragma unroll
                for (int r = 0; r < 4; ++r) s[nt][r] *= scale;
        }

        // ---- online softmax per row-half ----
#pragma unroll
        for (int half = 0; half < 2; ++half) {
            float mx = -INFINITY;
#pragma unroll
            for (int nt = 0; nt < 8; ++nt)
                mx = fmaxf(mx, fmaxf(s[nt][half * 2], s[nt][half * 2 + 1]));
            mx = fmaxf(mx, __shfl_xor_sync(0xffffffffu, mx, 1));
            mx = fmaxf(mx, __shfl_xor_sync(0xffffffffu, mx, 2));
            const float mnew  = fmaxf(m_r[half], mx);
            const float alpha = __expf(m_r[half] - mnew);
            float rs = 0.f;
#pragma unroll
            for (int nt = 0; nt < 8; ++nt) {
                float p0 = __expf(s[nt][half * 2]     - mnew);
                float p1 = __expf(s[nt][half * 2 + 1] - mnew);
                s[nt][half * 2]     = p0;
                s[nt][half * 2 + 1] = p1;
                rs += p0 + p1;
            }
            rs += __shfl_xor_sync(0xffffffffu, rs, 1);
            rs += __shfl_xor_sync(0xffffffffu, rs, 2);
            l_r[half] = l_r[half] * alpha + rs;
            m_r[half] = mnew;
#pragma unroll
            for (int nt = 0; nt < 8; ++nt) {
                yacc[nt][half * 2]     *= alpha;
                yacc[nt][half * 2 + 1] *= alpha;
            }
        }

        // ---- store P to smem (each warp owns its 16 rows) ----
#pragma unroll
        for (int nt = 0; nt < 8; ++nt) {
            const int c = nt * 8 + 2 * tig;
            float* p0 = sPQ + (wq + g) * APAD + c;
            p0[0] = s[nt][0]; p0[1] = s[nt][1];
            float* p1 = sPQ + (wq + g + 8) * APAD + c;
            p1[0] = s[nt][2]; p1[1] = s[nt][3];
        }
        __syncwarp();

        // ---- Y += P @ V, 3xTF32 ----
#pragma unroll
        for (int kt = 0; kt < 8; ++kt) {
            uint32_t ah[4], al[4];
            const float* base = sPQ + (wq + g) * APAD + kt * 8 + tig;
            split32(base[0],            ah[0], al[0]);
            split32(base[4],            ah[2], al[2]);
            split32(base[8 * APAD],     ah[1], al[1]);
            split32(base[8 * APAD + 4], ah[3], al[3]);
#pragma unroll
            for (int nt = 0; nt < 8; ++nt) {
                uint32_t bh[2], bl[2];
                const float* vb = sVT + (nt * 8 + g) * APAD + kt * 8 + tig;
                split32(vb[0], bh[0], bl[0]);
                split32(vb[4], bh[1], bl[1]);
                mma_tf32(yacc[nt], ah, bh);
                mma_tf32(yacc[nt], al, bh);
                mma_tf32(yacc[nt], ah, bl);
            }
        }
    }

    // ---- finalize: divide by l, write out ----
    const float inv0 = 1.f / l_r[0];
    const float inv1 = 1.f / l_r[1];
    const size_t o0 = qbase + (size_t)(wq + g) * EE;
    const size_t o1 = qbase + (size_t)(wq + g + 8) * EE;
#pragma unroll
    for (int nt = 0; nt < 8; ++nt) {
        const int c = nt * 8 + 2 * tig;
        y[o0 + c]     = yacc[nt][0] * inv0;
        y[o0 + c + 1] = yacc[nt][1] * inv0;
        y[o1 + c]     = yacc[nt][2] * inv1;
        y[o1 + c + 1] = yacc[nt][3] * inv1;
    }
}

// =====================================================================
// Host launcher
// =====================================================================
extern "C" void kernel_launch(void* const* d_in, const int* in_sizes, int n_in,
                              void* d_out, int out_size)
{
    (void)in_sizes; (void)n_in; (void)out_size;
    const float* q  = (const float*)d_in[0];
    // d_in[1] = external k: UNUSED (reference computes kp from qp — faithful quirk)
    const float* v  = (const float*)d_in[2];
    const float* Wq = (const float*)d_in[3];
    const float* Wk = (const float*)d_in[4];
    const float* Wv = (const float*)d_in[5];
    const float* Wp = (const float*)d_in[6];
    const float* bp = (const float*)d_in[7];
    float* out = (float*)d_out;

    float *qp, *kp, *vp, *yb;
    cudaGetSymbolAddress((void**)&qp, g_qp);
    cudaGetSymbolAddress((void**)&kp, g_kp);
    cudaGetSymbolAddress((void**)&vp, g_vp);
    cudaGetSymbolAddress((void**)&yb, g_y);

    cudaFuncSetAttribute(gemm_tn_kernel, cudaFuncAttributeMaxDynamicSharedMemorySize, GEMM_SMEM);
    cudaFuncSetAttribute(attn_kernel,    cudaFuncAttributeMaxDynamicSharedMemorySize, ATTN_SMEM);

    const dim3 gblk(256);
    const dim3 ggrd(EE / GBN, MM / GBM);   // (8, 64)

    // 1) qp = q @ Wq^T
    gemm_tn_kernel<<<ggrd, gblk, GEMM_SMEM>>>(q,  Wq, nullptr, qp, MM, EE, EE);
    // 2) kp = qp @ Wk^T   (faithful quirk)
    gemm_tn_kernel<<<ggrd, gblk, GEMM_SMEM>>>(qp, Wk, nullptr, kp, MM, EE, EE);
    // 3) vp = v @ Wv^T
    gemm_tn_kernel<<<ggrd, gblk, GEMM_SMEM>>>(v,  Wv, nullptr, vp, MM, EE, EE);
    // 4) causal flash attention, scale = +sqrt(D)
    attn_kernel<<<dim3(TT / 64, BB * HH), 128, ATTN_SMEM>>>(qp, kp, vp, yb);
    // 5) out = y @ Wp^T + bp
    gemm_tn_kernel<<<ggrd, gblk, GEMM_SMEM>>>(yb, Wp, bp, out, MM, EE, EE);
}

// round 5
// speedup vs baseline: 1.2102x; 1.2102x over previous
#include <cuda_runtime.h>
#include <cuda_bf16.h>
#include <cstdint>

// Problem constants
#define BB 4
#define TT 2048
#define EE 1024
#define HH 16
#define DD 64
#define MM (BB*TT)          // 8192

// ---------------- scratch: tf32 (hi,lo) pair arrays ----------------------
__device__ uint2 g_qs [(size_t)MM * EE];
__device__ uint2 g_vs [(size_t)MM * EE];
__device__ uint2 g_qps[(size_t)MM * EE];
__device__ uint2 g_kps[(size_t)MM * EE];
__device__ uint2 g_vps[(size_t)MM * EE];
__device__ uint2 g_ys [(size_t)MM * EE];
__device__ uint2 g_Wqs[(size_t)EE * EE];
__device__ uint2 g_Wks[(size_t)EE * EE];
__device__ uint2 g_Wvs[(size_t)EE * EE];
__device__ uint2 g_Wps[(size_t)EE * EE];

// ---------------- helpers -------------------------------------------------
__device__ __forceinline__ uint32_t f2tf32(float x) {
    uint32_t r;
    asm("cvt.rna.tf32.f32 %0, %1;" : "=r"(r) : "f"(x));
    return r;
}

__device__ __forceinline__ void split32(float x, uint32_t& hi, uint32_t& lo) {
    hi = f2tf32(x);
    lo = f2tf32(x - __uint_as_float(hi));
}

__device__ __forceinline__ void mma_tf32(float* c, const uint32_t* a, const uint32_t* b) {
    asm volatile(
        "mma.sync.aligned.m16n8k8.row.col.f32.tf32.tf32.f32 "
        "{%0,%1,%2,%3}, {%4,%5,%6,%7}, {%8,%9}, {%0,%1,%2,%3};\n"
        : "+f"(c[0]), "+f"(c[1]), "+f"(c[2]), "+f"(c[3])
        : "r"(a[0]), "r"(a[1]), "r"(a[2]), "r"(a[3]), "r"(b[0]), "r"(b[1]));
}

__device__ __forceinline__ void cp16(void* smem_dst, const void* gsrc) {
    unsigned d = (unsigned)__cvta_generic_to_shared(smem_dst);
    asm volatile("cp.async.cg.shared.global [%0], [%1], 16;\n" :: "r"(d), "l"(gsrc));
}
#define CP_COMMIT() asm volatile("cp.async.commit_group;\n")
#define CP_WAIT0()  asm volatile("cp.async.wait_group 0;\n")
#define CP_WAIT1()  asm volatile("cp.async.wait_group 1;\n")

__device__ __forceinline__ void ldpair(const uint32_t* smw, int off, uint32_t& hi, uint32_t& lo) {
    uint2 p = *reinterpret_cast<const uint2*>(smw + off);   // LDS.64
    hi = p.x; lo = p.y;
}

// =====================================================================
// Split kernel: f32 -> interleaved tf32 (hi,lo) pairs
// =====================================================================
__global__ void __launch_bounds__(256)
split_kernel(const float4* __restrict__ in, uint4* __restrict__ out, int n4)
{
    int i = blockIdx.x * blockDim.x + threadIdx.x;
    if (i >= n4) return;
    float4 v = in[i];
    uint4 o0, o1;
    split32(v.x, o0.x, o0.y); split32(v.y, o0.z, o0.w);
    split32(v.z, o1.x, o1.y); split32(v.w, o1.z, o1.w);
    out[2 * i]     = o0;
    out[2 * i + 1] = o1;
}

// =====================================================================
// GEMM on pre-split pairs: C[M,N] = A[M,K] @ B[N,K]^T (3xTF32)
// 128x128 block, 4 warps (64x64 each), GBK=16, double-buffered cp.async
// =====================================================================
#define GBK 16
#define GSW 40                       // words per smem row (32 data + 8 pad); 40%32==8 -> conflict free
#define GSTAGE (128 * GSW)           // words per stage per matrix
#define GEMM_SMEM (4 * GSTAGE * 4)   // 2 matrices x 2 stages = 81920 bytes

__global__ void __launch_bounds__(128, 2)
gemm_pp_kernel(const uint2* __restrict__ A,
               const uint2* __restrict__ B,
               const float* __restrict__ bias,
               uint2* __restrict__ Cp,
               float* __restrict__ Cf,
               int M, int N, int K)
{
    extern __shared__ uint32_t smw[];
    uint32_t* sA = smw;               // 2 stages
    uint32_t* sB = smw + 2 * GSTAGE;  // 2 stages

    const int t  = threadIdx.x;
    const int m0 = blockIdx.y * 128;
    const int n0 = blockIdx.x * 128;

    const int warp = t >> 5;
    const int lane = t & 31;
    const int g    = lane >> 2;
    const int tig  = lane & 3;
    const int wm   = (warp & 1) * 64;
    const int wn   = (warp >> 1) * 64;

    auto stage_load = [&](int s, int k0) {
        uint32_t* dA = sA + s * GSTAGE;
        uint32_t* dB = sB + s * GSTAGE;
        const uint2* gA = A + (size_t)(m0 + t) * K + k0;
        const uint2* gB = B + (size_t)(n0 + t) * K + k0;
#pragma unroll
        for (int ch = 0; ch < 8; ++ch) {
            cp16(dA + t * GSW + ch * 4, gA + ch * 2);
            cp16(dB + t * GSW + ch * 4, gB + ch * 2);
        }
        CP_COMMIT();
    };

    float acc[4][8][4];
#pragma unroll
    for (int mt = 0; mt < 4; ++mt)
#pragma unroll
        for (int nt = 0; nt < 8; ++nt)
#pragma unroll
            for (int r = 0; r < 4; ++r) acc[mt][nt][r] = 0.f;

    const int KT = K / GBK;   // 64
    stage_load(0, 0);
    stage_load(1, GBK);

    for (int kt = 0; kt < KT; ++kt) {
        const int s = kt & 1;
        CP_WAIT1();
        __syncthreads();
        const uint32_t* cA = sA + s * GSTAGE;
        const uint32_t* cB = sB + s * GSTAGE;
#pragma unroll
        for (int ks = 0; ks < 2; ++ks) {
            const int kk2 = 2 * (ks * 8 + tig);   // word offset of this thread's k
            uint32_t ah[4][4], al[4][4], bh[8][2], bl[8][2];
#pragma unroll
            for (int mt = 0; mt < 4; ++mt) {
                const int bw = (wm + mt * 16 + g) * GSW + kk2;
                ldpair(cA, bw,            ah[mt][0], al[mt][0]);
                ldpair(cA, bw + 8,        ah[mt][2], al[mt][2]);
                ldpair(cA, bw + 8 * GSW,     ah[mt][1], al[mt][1]);
                ldpair(cA, bw + 8 * GSW + 8, ah[mt][3], al[mt][3]);
            }
#pragma unroll
            for (int nt = 0; nt < 8; ++nt) {
                const int bw = (wn + nt * 8 + g) * GSW + kk2;
                ldpair(cB, bw,     bh[nt][0], bl[nt][0]);
                ldpair(cB, bw + 8, bh[nt][1], bl[nt][1]);
            }
            // term-major: long reuse distance per accumulator
#pragma unroll
            for (int mt = 0; mt < 4; ++mt)
#pragma unroll
                for (int nt = 0; nt < 8; ++nt)
                    mma_tf32(acc[mt][nt], ah[mt], bh[nt]);
#pragma unroll
            for (int mt = 0; mt < 4; ++mt)
#pragma unroll
                for (int nt = 0; nt < 8; ++nt)
                    mma_tf32(acc[mt][nt], al[mt], bh[nt]);
#pragma unroll
            for (int mt = 0; mt < 4; ++mt)
#pragma unroll
                for (int nt = 0; nt < 8; ++nt)
                    mma_tf32(acc[mt][nt], ah[mt], bl[nt]);
        }
        __syncthreads();
        if (kt + 2 < KT) stage_load(s, (kt + 2) * GBK);
        else CP_COMMIT();
    }

    // epilogue
#pragma unroll
    for (int mt = 0; mt < 4; ++mt) {
        const int r0 = m0 + wm + mt * 16 + g;
#pragma unroll
        for (int nt = 0; nt < 8; ++nt) {
            const int c = n0 + wn + nt * 8 + 2 * tig;
            if (Cf) {
                float b0 = bias ? bias[c]     : 0.f;
                float b1 = bias ? bias[c + 1] : 0.f;
                Cf[(size_t)r0 * N + c]           = acc[mt][nt][0] + b0;
                Cf[(size_t)r0 * N + c + 1]       = acc[mt][nt][1] + b1;
                Cf[(size_t)(r0 + 8) * N + c]     = acc[mt][nt][2] + b0;
                Cf[(size_t)(r0 + 8) * N + c + 1] = acc[mt][nt][3] + b1;
            } else {
                uint2 p;
                split32(acc[mt][nt][0], p.x, p.y); Cp[(size_t)r0 * N + c]           = p;
                split32(acc[mt][nt][1], p.x, p.y); Cp[(size_t)r0 * N + c + 1]       = p;
                split32(acc[mt][nt][2], p.x, p.y); Cp[(size_t)(r0 + 8) * N + c]     = p;
                split32(acc[mt][nt][3], p.x, p.y); Cp[(size_t)(r0 + 8) * N + c + 1] = p;
            }
        }
    }
}

// =====================================================================
// Flash attention (causal) on pre-split pairs, scale = +sqrt(D) = 8
// 64x64 tiles, 4 warps, staggered cp.async (V overlaps S, K+1 overlaps PV)
// =====================================================================
#define KVW 136                       // pair-row stride in words (128 data + 8 pad); 136%32==8
#define PPAD 68
#define ATTN_SMEM ((2 * 64 * KVW + 64 * PPAD) * 4)   // 87040 bytes

__device__ __forceinline__ void kv_load(uint32_t* dst, const uint2* __restrict__ src,
                                        size_t base_elem, int t)
{
#pragma unroll
    for (int i = 0; i < 16; ++i) {
        const int idx = t + i * 128;
        const int row = idx >> 5;
        const int ch  = idx & 31;
        cp16(dst + row * KVW + ch * 4, src + base_elem + (size_t)row * EE + ch * 2);
    }
}

__global__ void __launch_bounds__(128, 2)
attn_kernel(const uint2* __restrict__ qs,
            const uint2* __restrict__ ks,
            const uint2* __restrict__ vs,
            uint2* __restrict__ ys)
{
    extern __shared__ uint32_t smw[];
    uint32_t* sK = smw;                 // pairs [key][d]
    uint32_t* sV = smw + 64 * KVW;      // pairs [key][d] (row-major; B-frag loads conflict-free)
    float*    sP = (float*)(smw + 2 * 64 * KVW);   // f32 P [row][col] 64 x PPAD

    const int qi = (TT / 64 - 1) - blockIdx.x;   // reversed: heavy tiles first
    const int bh = blockIdx.y;
    const int b  = bh >> 4;
    const int h  = bh & 15;
    const int t  = threadIdx.x;
    const int warp = t >> 5, lane = t & 31;
    const int g = lane >> 2, tig = lane & 3;
    const int wq = warp * 16;

    const size_t qrow0 = (size_t)b * TT + (size_t)qi * 64;
    const size_t qbase = qrow0 * EE + h * DD;

    // ---- load Q pairs into sK (temporary), extract register fragments ----
    kv_load(sK, qs, qbase, t);
    CP_COMMIT();
    CP_WAIT0();
    __syncthreads();

    uint32_t qh[8][4], ql[8][4];
#pragma unroll
    for (int kt = 0; kt < 8; ++kt) {
        const int bw = (wq + g) * KVW + 2 * (kt * 8 + tig);
        ldpair(sK, bw,            qh[kt][0], ql[kt][0]);
        ldpair(sK, bw + 8,        qh[kt][2], ql[kt][2]);
        ldpair(sK, bw + 8 * KVW,     qh[kt][1], ql[kt][1]);
        ldpair(sK, bw + 8 * KVW + 8, qh[kt][3], ql[kt][3]);
    }
    __syncthreads();   // all warps done reading sK

    float m_r[2] = {-INFINITY, -INFINITY};
    float l_r[2] = {0.f, 0.f};
    float yacc[8][4];
#pragma unroll
    for (int nt = 0; nt < 8; ++nt)
#pragma unroll
        for (int r = 0; r < 4; ++r) yacc[nt][r] = 0.f;

    // preload K[0]
    kv_load(sK, ks, ((size_t)b * TT) * EE + h * DD, t);
    CP_COMMIT();

    for (int j = 0; j <= qi; ++j) {
        const size_t kvb = ((size_t)b * TT + (size_t)j * 64) * EE + h * DD;

        CP_WAIT0();          // K[j] arrived (this thread's chunks)
        __syncthreads();     // all threads' chunks visible; all warps done PV[j-1] (sV free)

        kv_load(sV, vs, kvb, t);   // V[j] overlaps S compute
        CP_COMMIT();

        // ---- S = Q K^T (16x64 per warp), 3xTF32 from pairs ----
        float s[8][4];
#pragma unroll
        for (int nt = 0; nt < 8; ++nt)
#pragma unroll
            for (int r = 0; r < 4; ++r) s[nt][r] = 0.f;
#pragma unroll
        for (int kt = 0; kt < 8; ++kt) {
            uint32_t kh[8][2], kl[8][2];
#pragma unroll
            for (int nt = 0; nt < 8; ++nt) {
                const int bw = (nt * 8 + g) * KVW + 2 * (kt * 8 + tig);
                ldpair(sK, bw,     kh[nt][0], kl[nt][0]);
                ldpair(sK, bw + 8, kh[nt][1], kl[nt][1]);
            }
#pragma unroll
            for (int nt = 0; nt < 8; ++nt) mma_tf32(s[nt], qh[kt], kh[nt]);
#pragma unroll
            for (int nt = 0; nt < 8; ++nt) mma_tf32(s[nt], ql[kt], kh[nt]);
#pragma unroll
            for (int nt = 0; nt < 8; ++nt) mma_tf32(s[nt], qh[kt], kl[nt]);
        }

        CP_WAIT0();          // V[j] arrived
        __syncthreads();     // visible to all; all warps done with sK

        if (j < qi) {        // K[j+1] overlaps softmax + PV
            kv_load(sK, ks, kvb + (size_t)64 * EE, t);
        }
        CP_COMMIT();

        // ---- scale (+mask on diagonal tile) ----
        const float scale = 8.0f;
        if (j == qi) {
            const int r0 = wq + g, r1 = wq + g + 8;
#pragma unroll
            for (int nt = 0; nt < 8; ++nt) {
                const int c = nt * 8 + 2 * tig;
                s[nt][0] = (c     <= r0) ? s[nt][0] * scale : -INFINITY;
                s[nt][1] = (c + 1 <= r0) ? s[nt][1] * scale : -INFINITY;
                s[nt][2] = (c     <= r1) ? s[nt][2] * scale : -INFINITY;
                s[nt][3] = (c + 1 <= r1) ? s[nt][3] * scale : -INFINITY;
            }
        } else {
#pragma unroll
            for (int nt = 0; nt < 8; ++nt)
#pragma unroll
                for (int r = 0; r < 4; ++r) s[nt][r] *= scale;
        }

        // ---- online softmax per row-half ----
#pragma unroll
        for (int half = 0; half < 2; ++half) {
            float mx = -INFINITY;
#pragma unroll
            for (int nt = 0; nt < 8; ++nt)
                mx = fmaxf(mx, fmaxf(s[nt][half * 2], s[nt][half * 2 + 1]));
            mx = fmaxf(mx, __shfl_xor_sync(0xffffffffu, mx, 1));
            mx = fmaxf(mx, __shfl_xor_sync(0xffffffffu, mx, 2));
            const float mnew  = fmaxf(m_r[half], mx);
            const float alpha = __expf(m_r[half] - mnew);
            float rs = 0.f;
#pragma unroll
            for (int nt = 0; nt < 8; ++nt) {
                float p0 = __expf(s[nt][half * 2]     - mnew);
                float p1 = __expf(s[nt][half * 2 + 1] - mnew);
                s[nt][half * 2]     = p0;
                s[nt][half * 2 + 1] = p1;
                rs += p0 + p1;
            }
            rs += __shfl_xor_sync(0xffffffffu, rs, 1);
            rs += __shfl_xor_sync(0xffffffffu, rs, 2);
            l_r[half] = l_r[half] * alpha + rs;
            m_r[half] = mnew;
#pragma unroll
            for (int nt = 0; nt < 8; ++nt) {
                yacc[nt][half * 2]     *= alpha;
                yacc[nt][half * 2 + 1] *= alpha;
            }
        }

        // ---- store P (warp-private rows) ----
#pragma unroll
        for (int nt = 0; nt < 8; ++nt) {
            const int c = nt * 8 + 2 * tig;
            float* p0 = sP + (wq + g) * PPAD + c;
            p0[0] = s[nt][0]; p0[1] = s[nt][1];
            float* p1 = sP + (wq + g + 8) * PPAD + c;
            p1[0] = s[nt][2]; p1[1] = s[nt][3];
        }
        __syncwarp();

        // ---- Y += P @ V, 3xTF32 (P split on the fly, V from pairs) ----
#pragma unroll
        for (int kt = 0; kt < 8; ++kt) {
            uint32_t ah[4], al[4];
            const float* base = sP + (wq + g) * PPAD + kt * 8 + tig;
            split32(base[0],            ah[0], al[0]);
            split32(base[4],            ah[2], al[2]);
            split32(base[8 * PPAD],     ah[1], al[1]);
            split32(base[8 * PPAD + 4], ah[3], al[3]);
            uint32_t vh[8][2], vl[8][2];
#pragma unroll
            for (int nt = 0; nt < 8; ++nt) {
                const int w0 = (kt * 8 + tig) * KVW     + 2 * (nt * 8 + g);
                const int w1 = (kt * 8 + tig + 4) * KVW + 2 * (nt * 8 + g);
                ldpair(sV, w0, vh[nt][0], vl[nt][0]);
                ldpair(sV, w1, vh[nt][1], vl[nt][1]);
            }
#pragma unroll
            for (int nt = 0; nt < 8; ++nt) mma_tf32(yacc[nt], ah, vh[nt]);
#pragma unroll
            for (int nt = 0; nt < 8; ++nt) mma_tf32(yacc[nt], al, vh[nt]);
#pragma unroll
            for (int nt = 0; nt < 8; ++nt) mma_tf32(yacc[nt], ah, vl[nt]);
        }
    }

    // ---- finalize: divide by l, write pair output ----
    const float inv0 = 1.f / l_r[0];
    const float inv1 = 1.f / l_r[1];
    const size_t o0 = qbase + (size_t)(wq + g) * EE;
    const size_t o1 = qbase + (size_t)(wq + g + 8) * EE;
#pragma unroll
    for (int nt = 0; nt < 8; ++nt) {
        const int c = nt * 8 + 2 * tig;
        uint2 p;
        split32(yacc[nt][0] * inv0, p.x, p.y); ys[o0 + c]     = p;
        split32(yacc[nt][1] * inv0, p.x, p.y); ys[o0 + c + 1] = p;
        split32(yacc[nt][2] * inv1, p.x, p.y); ys[o1 + c]     = p;
        split32(yacc[nt][3] * inv1, p.x, p.y); ys[o1 + c + 1] = p;
    }
}

// =====================================================================
// Host launcher
// =====================================================================
extern "C" void kernel_launch(void* const* d_in, const int* in_sizes, int n_in,
                              void* d_out, int out_size)
{
    (void)in_sizes; (void)n_in; (void)out_size;
    const float* q  = (const float*)d_in[0];
    // d_in[1] = external k: UNUSED (reference computes kp from qp — faithful quirk)
    const float* v  = (const float*)d_in[2];
    const float* Wq = (const float*)d_in[3];
    const float* Wk = (const float*)d_in[4];
    const float* Wv = (const float*)d_in[5];
    const float* Wp = (const float*)d_in[6];
    const float* bp = (const float*)d_in[7];
    float* out = (float*)d_out;

    uint2 *qs, *vs, *qps, *kps, *vps, *ys, *Wqs, *Wks, *Wvs, *Wps;
    cudaGetSymbolAddress((void**)&qs,  g_qs);
    cudaGetSymbolAddress((void**)&vs,  g_vs);
    cudaGetSymbolAddress((void**)&qps, g_qps);
    cudaGetSymbolAddress((void**)&kps, g_kps);
    cudaGetSymbolAddress((void**)&vps, g_vps);
    cudaGetSymbolAddress((void**)&ys,  g_ys);
    cudaGetSymbolAddress((void**)&Wqs, g_Wqs);
    cudaGetSymbolAddress((void**)&Wks, g_Wks);
    cudaGetSymbolAddress((void**)&Wvs, g_Wvs);
    cudaGetSymbolAddress((void**)&Wps, g_Wps);

    cudaFuncSetAttribute(gemm_pp_kernel, cudaFuncAttributeMaxDynamicSharedMemorySize, GEMM_SMEM);
    cudaFuncSetAttribute(attn_kernel,    cudaFuncAttributeMaxDynamicSharedMemorySize, ATTN_SMEM);

    const int nM4 = (MM * EE) / 4;   // activations
    const int nW4 = (EE * EE) / 4;   // weights
    split_kernel<<<nM4 / 256, 256>>>((const float4*)q,  (uint4*)qs,  nM4);
    split_kernel<<<nM4 / 256, 256>>>((const float4*)v,  (uint4*)vs,  nM4);
    split_kernel<<<nW4 / 256, 256>>>((const float4*)Wq, (uint4*)Wqs, nW4);
    split_kernel<<<nW4 / 256, 256>>>((const float4*)Wk, (uint4*)Wks, nW4);
    split_kernel<<<nW4 / 256, 256>>>((const float4*)Wv, (uint4*)Wvs, nW4);
    split_kernel<<<nW4 / 256, 256>>>((const float4*)Wp, (uint4*)Wps, nW4);

    const dim3 gblk(128);
    const dim3 ggrd(EE / 128, MM / 128);   // (8, 64)

    // 1) qp = q @ Wq^T        (pair output)
    gemm_pp_kernel<<<ggrd, gblk, GEMM_SMEM>>>(qs,  Wqs, nullptr, qps, nullptr, MM, EE, EE);
    // 2) kp = qp @ Wk^T       (faithful quirk; pair output)
    gemm_pp_kernel<<<ggrd, gblk, GEMM_SMEM>>>(qps, Wks, nullptr, kps, nullptr, MM, EE, EE);
    // 3) vp = v @ Wv^T        (pair output)
    gemm_pp_kernel<<<ggrd, gblk, GEMM_SMEM>>>(vs,  Wvs, nullptr, vps, nullptr, MM, EE, EE);
    // 4) causal flash attention, scale = +sqrt(D); writes pair y
    attn_kernel<<<dim3(TT / 64, BB * HH), 128, ATTN_SMEM>>>(qps, kps, vps, ys);
    // 5) out = y @ Wp^T + bp  (f32 output)
    gemm_pp_kernel<<<ggrd, gblk, GEMM_SMEM>>>(ys, Wps, bp, nullptr, out, MM, EE, EE);
}

// round 7
// speedup vs baseline: 2.6820x; 2.2161x over previous
#include <cuda_runtime.h>
#include <cuda_bf16.h>
#include <cstdint>

// Problem constants
#define BB 4
#define TT 2048
#define EE 1024
#define HH 16
#define DD 64
#define MM (BB*TT)                 // 8192
#define NELEM ((size_t)MM * EE)    // 8388608
#define WELEM ((size_t)EE * EE)    // 1048576

// ---------------- scratch: bf16 hi/mid planes (no runtime alloc) ----------
__device__ uint16_t g_qh [NELEM], g_qm [NELEM];   // split of input q
__device__ uint16_t g_vh [NELEM], g_vm [NELEM];   // split of input v
__device__ uint16_t g_qph[NELEM], g_qpm[NELEM];   // qp (row-major)
__device__ uint16_t g_kph[NELEM], g_kpm[NELEM];   // kp (row-major)
__device__ uint16_t g_vth[NELEM], g_vtm[NELEM];   // vp TRANSPOSED: [(b,h,d)][t]
__device__ uint16_t g_yh [NELEM], g_ym [NELEM];   // attention output y
__device__ uint16_t g_Wqh[WELEM], g_Wqm[WELEM];
__device__ uint16_t g_Wkh[WELEM], g_Wkm[WELEM];
__device__ uint16_t g_Wvh[WELEM], g_Wvm[WELEM];
__device__ uint16_t g_Wph[WELEM], g_Wpm[WELEM];

// ---------------- helpers -------------------------------------------------
__device__ __forceinline__ uint32_t pack_bf2(float x1, float x0) {
    // result: upper half = bf16(x1), lower half = bf16(x0)
    uint32_t r;
    asm("cvt.rn.bf16x2.f32 %0, %1, %2;" : "=r"(r) : "f"(x1), "f"(x0));
    return r;
}
// split two floats (x0 = even-k, x1 = odd-k) into packed hi and mid bf16x2
__device__ __forceinline__ uint2 split2(float x0, float x1) {
    uint32_t h = pack_bf2(x1, x0);
    float f0 = __uint_as_float(h << 16);
    float f1 = __uint_as_float(h & 0xffff0000u);
    uint32_t m = pack_bf2(x1 - f1, x0 - f0);
    return make_uint2(h, m);
}
__device__ __forceinline__ void mma_bf16(float* c, const uint32_t* a, const uint32_t* b) {
    asm volatile(
        "mma.sync.aligned.m16n8k16.row.col.f32.bf16.bf16.f32 "
        "{%0,%1,%2,%3}, {%4,%5,%6,%7}, {%8,%9}, {%0,%1,%2,%3};\n"
        : "+f"(c[0]), "+f"(c[1]), "+f"(c[2]), "+f"(c[3])
        : "r"(a[0]), "r"(a[1]), "r"(a[2]), "r"(a[3]), "r"(b[0]), "r"(b[1]));
}
__device__ __forceinline__ void cp16(void* smem_dst, const void* gsrc) {
    unsigned d = (unsigned)__cvta_generic_to_shared(smem_dst);
    asm volatile("cp.async.cg.shared.global [%0], [%1], 16;\n" :: "r"(d), "l"(gsrc));
}
#define CP_COMMIT() asm volatile("cp.async.commit_group;\n")
#define CP_WAIT0()  asm volatile("cp.async.wait_group 0;\n")
#define CP_WAIT1()  asm volatile("cp.async.wait_group 1;\n")

// =====================================================================
// Split kernels: f32 -> bf16 hi/mid planes
// =====================================================================
#define Q4 ((int)(NELEM / 4))
#define W4 ((int)(WELEM / 4))

__device__ __forceinline__ void split_store(const float4* in, uint32_t* oh, uint32_t* om, int idx) {
    float4 x = in[idx];
    uint2 p0 = split2(x.x, x.y);
    uint2 p1 = split2(x.z, x.w);
    *reinterpret_cast<uint2*>(oh + 2 * idx) = make_uint2(p0.x, p1.x);
    *reinterpret_cast<uint2*>(om + 2 * idx) = make_uint2(p0.y, p1.y);
}

__global__ void __launch_bounds__(256)
split_w_kernel(const float4* __restrict__ Wq, const float4* __restrict__ Wk,
               const float4* __restrict__ Wv, const float4* __restrict__ Wp,
               uint32_t* __restrict__ wqh, uint32_t* __restrict__ wqm,
               uint32_t* __restrict__ wkh, uint32_t* __restrict__ wkm,
               uint32_t* __restrict__ wvh, uint32_t* __restrict__ wvm,
               uint32_t* __restrict__ wph, uint32_t* __restrict__ wpm)
{
    int i = blockIdx.x * blockDim.x + threadIdx.x;
    if (i >= 4 * W4) return;
    if (i < W4)          split_store(Wq, wqh, wqm, i);
    else if (i < 2 * W4) split_store(Wk, wkh, wkm, i - W4);
    else if (i < 3 * W4) split_store(Wv, wvh, wvm, i - 2 * W4);
    else                 split_store(Wp, wph, wpm, i - 3 * W4);
}

__global__ void __launch_bounds__(256)
split_act_kernel(const float4* __restrict__ q, const float4* __restrict__ v,
                 uint32_t* __restrict__ qh, uint32_t* __restrict__ qm,
                 uint32_t* __restrict__ vh, uint32_t* __restrict__ vm)
{
    int i = blockIdx.x * blockDim.x + threadIdx.x;
    if (i >= 2 * Q4) return;
    if (i < Q4) split_store(q, qh, qm, i);
    else        split_store(v, vh, vm, i - Q4);
}

// =====================================================================
// GEMM: C[M,N] = A[M,K] @ B[N,K]^T, 3xBF16 from hi/mid planes
// 128x128 block, 4 warps (64x64 warptile), K-chunk 32, double-buffered
// mode: 0 -> hi/mid planes row-major; 1 -> V^T planes; 2 -> f32 + bias
// =====================================================================
#define GSW 20                      // words per 32-bf16 row (16 data + 4 pad); (20g+tig)%32 conflict-free
#define GPLANE (128 * GSW)          // 2560 words per plane tile
#define GSTAGE (4 * GPLANE)         // Ah, Am, Bh, Bm
#define GEMM_SMEM (2 * GSTAGE * 4)  // 81920 bytes (epilogue staging aliases this)
#define STG_W 133

__global__ void __launch_bounds__(128, 2)
gemm_bf_kernel(const uint16_t* __restrict__ Ah, const uint16_t* __restrict__ Am,
               const uint16_t* __restrict__ Bh, const uint16_t* __restrict__ Bm,
               const float* __restrict__ bias, int mode,
               uint32_t* __restrict__ OH, uint32_t* __restrict__ OM,
               float* __restrict__ OF)
{
    extern __shared__ uint32_t smw[];
    const int t    = threadIdx.x;
    const int warp = t >> 5;
    const int lane = t & 31;
    const int g    = lane >> 2;
    const int tig  = lane & 3;
    const int m0 = blockIdx.y * 128;
    const int n0 = blockIdx.x * 128;
    const int wm = (warp & 1) * 64;
    const int wn = (warp >> 1) * 64;

    auto stage_load = [&](int s, int k0) {
        uint32_t* base = smw + s * GSTAGE;
        const uint16_t* srcs[4] = {
            Ah + (size_t)(m0 + t) * EE + k0, Am + (size_t)(m0 + t) * EE + k0,
            Bh + (size_t)(n0 + t) * EE + k0, Bm + (size_t)(n0 + t) * EE + k0 };
#pragma unroll
        for (int p = 0; p < 4; ++p)
#pragma unroll
            for (int j = 0; j < 4; ++j)
                cp16(base + p * GPLANE + t * GSW + j * 4, srcs[p] + j * 8);
        CP_COMMIT();
    };

    float acc[4][8][4];
#pragma unroll
    for (int mt = 0; mt < 4; ++mt)
#pragma unroll
        for (int nt = 0; nt < 8; ++nt)
#pragma unroll
            for (int r = 0; r < 4; ++r) acc[mt][nt][r] = 0.f;

    stage_load(0, 0);
    stage_load(1, 32);

    const int NCH = EE / 32;   // 32
    for (int c = 0; c < NCH; ++c) {
        const int s = c & 1;
        if (c >= NCH - 2) CP_WAIT0(); else CP_WAIT1();
        __syncthreads();
        const uint32_t* S = smw + s * GSTAGE;
#pragma unroll
        for (int ks = 0; ks < 2; ++ks) {
            uint32_t ah[4][4], am[4][4], bh[8][2], bm[8][2];
#pragma unroll
            for (int mt = 0; mt < 4; ++mt) {
                const int bw = (wm + mt * 16 + g) * GSW + ks * 8 + tig;
                ah[mt][0] = S[bw];                ah[mt][1] = S[bw + 8 * GSW];
                ah[mt][2] = S[bw + 4];            ah[mt][3] = S[bw + 8 * GSW + 4];
                am[mt][0] = S[GPLANE + bw];       am[mt][1] = S[GPLANE + bw + 8 * GSW];
                am[mt][2] = S[GPLANE + bw + 4];   am[mt][3] = S[GPLANE + bw + 8 * GSW + 4];
            }
#pragma unroll
            for (int nt = 0; nt < 8; ++nt) {
                const int bw = (wn + nt * 8 + g) * GSW + ks * 8 + tig;
                bh[nt][0] = S[2 * GPLANE + bw];   bh[nt][1] = S[2 * GPLANE + bw + 4];
                bm[nt][0] = S[3 * GPLANE + bw];   bm[nt][1] = S[3 * GPLANE + bw + 4];
            }
#pragma unroll
            for (int mt = 0; mt < 4; ++mt)
#pragma unroll
                for (int nt = 0; nt < 8; ++nt)
                    mma_bf16(acc[mt][nt], ah[mt], bh[nt]);
#pragma unroll
            for (int mt = 0; mt < 4; ++mt)
#pragma unroll
                for (int nt = 0; nt < 8; ++nt)
                    mma_bf16(acc[mt][nt], am[mt], bh[nt]);
#pragma unroll
            for (int mt = 0; mt < 4; ++mt)
#pragma unroll
                for (int nt = 0; nt < 8; ++nt)
                    mma_bf16(acc[mt][nt], ah[mt], bm[nt]);
        }
        __syncthreads();
        if (c + 2 < NCH) stage_load(s, (c + 2) * 32);
        else CP_COMMIT();
    }

    // ---- epilogue: stage f32 result to smem, then coalesced writes ----
    float* stg = (float*)smw;
#pragma unroll
    for (int mt = 0; mt < 4; ++mt) {
        const int r0 = wm + mt * 16 + g;
#pragma unroll
        for (int nt = 0; nt < 8; ++nt) {
            const int c = wn + nt * 8 + 2 * tig;
            stg[r0 * STG_W + c]           = acc[mt][nt][0];
            stg[r0 * STG_W + c + 1]       = acc[mt][nt][1];
            stg[(r0 + 8) * STG_W + c]     = acc[mt][nt][2];
            stg[(r0 + 8) * STG_W + c + 1] = acc[mt][nt][3];
        }
    }
    __syncthreads();

    if (mode == 0) {            // hi/mid planes, row-major [m][e]
        for (int r = warp; r < 128; r += 4) {
            const size_t o = ((size_t)(m0 + r) * EE + n0) >> 1;   // u32 index
            float x0 = stg[r * STG_W + 2 * lane];
            float x1 = stg[r * STG_W + 2 * lane + 1];
            uint2 p = split2(x0, x1);
            OH[o + lane] = p.x; OM[o + lane] = p.y;
            x0 = stg[r * STG_W + 64 + 2 * lane];
            x1 = stg[r * STG_W + 64 + 2 * lane + 1];
            p = split2(x0, x1);
            OH[o + 32 + lane] = p.x; OM[o + 32 + lane] = p.y;
        }
    } else if (mode == 1) {     // V^T planes: [(b*16+h)*64 + d][t]
        const int b  = m0 >> 11;
        const int t0 = m0 & 2047;
        for (int c = warp; c < 128; c += 4) {
            const int e = n0 + c;
            const int h = e >> 6, d = e & 63;
            const size_t o = ((((size_t)b * HH + h) * DD + d) * TT + t0) >> 1;
            float x0 = stg[(2 * lane) * STG_W + c];
            float x1 = stg[(2 * lane + 1) * STG_W + c];
            uint2 p = split2(x0, x1);
            OH[o + lane] = p.x; OM[o + lane] = p.y;
            x0 = stg[(2 * lane + 64) * STG_W + c];
            x1 = stg[(2 * lane + 65) * STG_W + c];
            p = split2(x0, x1);
            OH[o + 32 + lane] = p.x; OM[o + 32 + lane] = p.y;
        }
    } else {                    // f32 + bias
        for (int r = warp; r < 128; r += 4) {
            const size_t o = (size_t)(m0 + r) * EE + n0;
#pragma unroll
            for (int qd = 0; qd < 4; ++qd) {
                const int c = lane + 32 * qd;
                OF[o + c] = stg[r * STG_W + c] + bias[n0 + c];
            }
        }
    }
}

// =====================================================================
// Flash attention (causal), scale = +sqrt(D) = 8 (faithful quirk)
// bf16x3 mma, 64x64 tiles, 4 warps; K row-major, V pre-transposed;
// P stays in registers (S-output layout == PV A-fragment layout for k16)
// =====================================================================
#define ASW 36                       // words per 64-bf16 row (32 data + 4 pad)
#define APLANE (64 * ASW)            // 2304 words
#define ATILE  (2 * APLANE)          // hi + mid
#define ATTN_SMEM (2 * ATILE * 4)    // sK + sV = 36864 bytes

__device__ __forceinline__ void tile_load(uint32_t* dstw,
                                          const uint16_t* __restrict__ hp,
                                          const uint16_t* __restrict__ mp,
                                          size_t base, int rstride, int t)
{
#pragma unroll
    for (int i = 0; i < 8; ++i) {
        const int idx = t + i * 128;
        const int p   = idx >> 9;
        const int rem = idx & 511;
        const int row = rem >> 3;
        const int ch  = rem & 7;
        const uint16_t* src = (p ? mp : hp) + base + (size_t)row * rstride + ch * 8;
        cp16(dstw + p * APLANE + row * ASW + ch * 4, src);
    }
}

__global__ void __launch_bounds__(128, 2)
attn_kernel(const uint16_t* __restrict__ qph, const uint16_t* __restrict__ qpm,
            const uint16_t* __restrict__ kph, const uint16_t* __restrict__ kpm,
            const uint16_t* __restrict__ vth, const uint16_t* __restrict__ vtm,
            uint32_t* __restrict__ YH, uint32_t* __restrict__ YM)
{
    extern __shared__ uint32_t smw[];
    uint32_t* sK = smw;            // K tile (hi+mid), also Q staging
    uint32_t* sV = smw + ATILE;    // V^T tile (hi+mid)

    const int qi = (TT / 64 - 1) - blockIdx.x;   // heavy tiles first
    const int bh = blockIdx.y;
    const int b  = bh >> 4;
    const int h  = bh & 15;
    const int t  = threadIdx.x;
    const int warp = t >> 5, lane = t & 31;
    const int g = lane >> 2, tig = lane & 3;
    const int wq = warp * 16;

    const size_t qbase  = ((size_t)b * TT + (size_t)qi * 64) * EE + h * DD;
    const size_t vtbase = (((size_t)b * HH + h) * DD) * TT;

    // ---- Q tile -> registers (through sK staging) ----
    tile_load(sK, qph, qpm, qbase, EE, t);
    CP_COMMIT(); CP_WAIT0();
    __syncthreads();

    uint32_t qAh[4][4], qAm[4][4];
#pragma unroll
    for (int kt = 0; kt < 4; ++kt) {
        const int bw = (wq + g) * ASW + kt * 8 + tig;
        qAh[kt][0] = sK[bw];               qAh[kt][1] = sK[bw + 8 * ASW];
        qAh[kt][2] = sK[bw + 4];           qAh[kt][3] = sK[bw + 8 * ASW + 4];
        qAm[kt][0] = sK[APLANE + bw];      qAm[kt][1] = sK[APLANE + bw + 8 * ASW];
        qAm[kt][2] = sK[APLANE + bw + 4];  qAm[kt][3] = sK[APLANE + bw + 8 * ASW + 4];
    }
    __syncthreads();

    float m_r[2] = {-INFINITY, -INFINITY};
    float l_r[2] = {0.f, 0.f};
    float yacc[8][4];
#pragma unroll
    for (int nt = 0; nt < 8; ++nt)
#pragma unroll
        for (int r = 0; r < 4; ++r) yacc[nt][r] = 0.f;

    // preload K[0]
    tile_load(sK, kph, kpm, ((size_t)b * TT) * EE + h * DD, EE, t);
    CP_COMMIT();

    for (int j = 0; j <= qi; ++j) {
        CP_WAIT0();          // K[j] arrived
        __syncthreads();     // visible to all; all warps done PV[j-1]

        tile_load(sV, vth, vtm, vtbase + (size_t)j * 64, TT, t);   // V[j] overlaps S
        CP_COMMIT();

        // ---- S = Q K^T (16x64 per warp), bf16x3 ----
        float s[8][4];
#pragma unroll
        for (int nt = 0; nt < 8; ++nt)
#pragma unroll
            for (int r = 0; r < 4; ++r) s[nt][r] = 0.f;
#pragma unroll
        for (int kt = 0; kt < 4; ++kt) {
            uint32_t kh[8][2], km[8][2];
#pragma unroll
            for (int nt = 0; nt < 8; ++nt) {
                const int bw = (nt * 8 + g) * ASW + kt * 8 + tig;
                kh[nt][0] = sK[bw];          kh[nt][1] = sK[bw + 4];
                km[nt][0] = sK[APLANE + bw]; km[nt][1] = sK[APLANE + bw + 4];
            }
#pragma unroll
            for (int nt = 0; nt < 8; ++nt) mma_bf16(s[nt], qAh[kt], kh[nt]);
#pragma unroll
            for (int nt = 0; nt < 8; ++nt) mma_bf16(s[nt], qAm[kt], kh[nt]);
#pragma unroll
            for (int nt = 0; nt < 8; ++nt) mma_bf16(s[nt], qAh[kt], km[nt]);
        }

        CP_WAIT0();          // V[j] arrived
        __syncthreads();     // all warps done with sK

        if (j < qi) tile_load(sK, kph, kpm, ((size_t)b * TT + (size_t)(j + 1) * 64) * EE + h * DD, EE, t);
        CP_COMMIT();

        // ---- scale (+mask on diagonal tile); scale = +sqrt(D) quirk ----
        const float scale = 8.0f;
        if (j == qi) {
            const int r0 = wq + g, r1 = wq + g + 8;
#pragma unroll
            for (int nt = 0; nt < 8; ++nt) {
                const int c = nt * 8 + 2 * tig;
                s[nt][0] = (c     <= r0) ? s[nt][0] * scale : -INFINITY;
                s[nt][1] = (c + 1 <= r0) ? s[nt][1] * scale : -INFINITY;
                s[nt][2] = (c     <= r1) ? s[nt][2] * scale : -INFINITY;
                s[nt][3] = (c + 1 <= r1) ? s[nt][3] * scale : -INFINITY;
            }
        } else {
#pragma unroll
            for (int nt = 0; nt < 8; ++nt)
#pragma unroll
                for (int r = 0; r < 4; ++r) s[nt][r] *= scale;
        }

        // ---- online softmax per row-half ----
#pragma unroll
        for (int half = 0; half < 2; ++half) {
            float mx = -INFINITY;
#pragma unroll
            for (int nt = 0; nt < 8; ++nt)
                mx = fmaxf(mx, fmaxf(s[nt][half * 2], s[nt][half * 2 + 1]));
            mx = fmaxf(mx, __shfl_xor_sync(0xffffffffu, mx, 1));
            mx = fmaxf(mx, __shfl_xor_sync(0xffffffffu, mx, 2));
            const float mnew  = fmaxf(m_r[half], mx);
            const float alpha = __expf(m_r[half] - mnew);
            float rs = 0.f;
#pragma unroll
            for (int nt = 0; nt < 8; ++nt) {
                float p0 = __expf(s[nt][half * 2]     - mnew);
                float p1 = __expf(s[nt][half * 2 + 1] - mnew);
                s[nt][half * 2]     = p0;
                s[nt][half * 2 + 1] = p1;
                rs += p0 + p1;
            }
            rs += __shfl_xor_sync(0xffffffffu, rs, 1);
            rs += __shfl_xor_sync(0xffffffffu, rs, 2);
            l_r[half] = l_r[half] * alpha + rs;
            m_r[half] = mnew;
#pragma unroll
            for (int nt = 0; nt < 8; ++nt) {
                yacc[nt][half * 2]     *= alpha;
                yacc[nt][half * 2 + 1] *= alpha;
            }
        }

        // ---- Y += P @ V : P built in-register (no smem round-trip) ----
#pragma unroll
        for (int kt = 0; kt < 4; ++kt) {
            uint32_t ph[4], pm[4];
            uint2 p;
            p = split2(s[2 * kt][0],     s[2 * kt][1]);     ph[0] = p.x; pm[0] = p.y;
            p = split2(s[2 * kt][2],     s[2 * kt][3]);     ph[1] = p.x; pm[1] = p.y;
            p = split2(s[2 * kt + 1][0], s[2 * kt + 1][1]); ph[2] = p.x; pm[2] = p.y;
            p = split2(s[2 * kt + 1][2], s[2 * kt + 1][3]); ph[3] = p.x; pm[3] = p.y;
            uint32_t vh[8][2], vm[8][2];
#pragma unroll
            for (int nt = 0; nt < 8; ++nt) {
                const int bw = (nt * 8 + g) * ASW + kt * 8 + tig;
                vh[nt][0] = sV[bw];          vh[nt][1] = sV[bw + 4];
                vm[nt][0] = sV[APLANE + bw]; vm[nt][1] = sV[APLANE + bw + 4];
            }
#pragma unroll
            for (int nt = 0; nt < 8; ++nt) mma_bf16(yacc[nt], ph, vh[nt]);
#pragma unroll
            for (int nt = 0; nt < 8; ++nt) mma_bf16(yacc[nt], pm, vh[nt]);
#pragma unroll
            for (int nt = 0; nt < 8; ++nt) mma_bf16(yacc[nt], ph, vm[nt]);
        }
    }

    // ---- finalize: divide by l, write hi/mid planes (paired u32 stores) ----
    const float inv0 = 1.f / l_r[0];
    const float inv1 = 1.f / l_r[1];
    const size_t o0 = qbase + (size_t)(wq + g) * EE;
    const size_t o1 = qbase + (size_t)(wq + g + 8) * EE;
#pragma unroll
    for (int nt = 0; nt < 8; ++nt) {
        const int c = nt * 8 + 2 * tig;
        uint2 p = split2(yacc[nt][0] * inv0, yacc[nt][1] * inv0);
        YH[(o0 + c) >> 1] = p.x; YM[(o0 + c) >> 1] = p.y;
        p = split2(yacc[nt][2] * inv1, yacc[nt][3] * inv1);
        YH[(o1 + c) >> 1] = p.x; YM[(o1 + c) >> 1] = p.y;
    }
}

// =====================================================================
// Host launcher — 7 launches; launch #5 (0-based) = attn for ncu -s 5
// =====================================================================
extern "C" void kernel_launch(void* const* d_in, const int* in_sizes, int n_in,
                              void* d_out, int out_size)
{
    (void)in_sizes; (void)n_in; (void)out_size;
    const float* q  = (const float*)d_in[0];
    // d_in[1] = external k: UNUSED (reference computes kp from qp — faithful quirk)
    const float* v  = (const float*)d_in[2];
    const float* Wq = (const float*)d_in[3];
    const float* Wk = (const float*)d_in[4];
    const float* Wv = (const float*)d_in[5];
    const float* Wp = (const float*)d_in[6];
    const float* bp = (const float*)d_in[7];
    float* out = (float*)d_out;

    uint16_t *qh,*qm,*vh,*vm,*qph,*qpm,*kph,*kpm,*vth,*vtm,*yh,*ym;
    uint16_t *Wqh,*Wqm,*Wkh,*Wkm,*Wvh,*Wvm,*Wph,*Wpm;
    cudaGetSymbolAddress((void**)&qh,  g_qh);  cudaGetSymbolAddress((void**)&qm,  g_qm);
    cudaGetSymbolAddress((void**)&vh,  g_vh);  cudaGetSymbolAddress((void**)&vm,  g_vm);
    cudaGetSymbolAddress((void**)&qph, g_qph); cudaGetSymbolAddress((void**)&qpm, g_qpm);
    cudaGetSymbolAddress((void**)&kph, g_kph); cudaGetSymbolAddress((void**)&kpm, g_kpm);
    cudaGetSymbolAddress((void**)&vth, g_vth); cudaGetSymbolAddress((void**)&vtm, g_vtm);
    cudaGetSymbolAddress((void**)&yh,  g_yh);  cudaGetSymbolAddress((void**)&ym,  g_ym);
    cudaGetSymbolAddress((void**)&Wqh, g_Wqh); cudaGetSymbolAddress((void**)&Wqm, g_Wqm);
    cudaGetSymbolAddress((void**)&Wkh, g_Wkh); cudaGetSymbolAddress((void**)&Wkm, g_Wkm);
    cudaGetSymbolAddress((void**)&Wvh, g_Wvh); cudaGetSymbolAddress((void**)&Wvm, g_Wvm);
    cudaGetSymbolAddress((void**)&Wph, g_Wph); cudaGetSymbolAddress((void**)&Wpm, g_Wpm);

    cudaFuncSetAttribute(gemm_bf_kernel, cudaFuncAttributeMaxDynamicSharedMemorySize, GEMM_SMEM);
    cudaFuncSetAttribute(attn_kernel,    cudaFuncAttributeMaxDynamicSharedMemorySize, ATTN_SMEM);

    // 0) weight splits
    split_w_kernel<<<(4 * W4 + 255) / 256, 256>>>(
        (const float4*)Wq, (const float4*)Wk, (const float4*)Wv, (const float4*)Wp,
        (uint32_t*)Wqh, (uint32_t*)Wqm, (uint32_t*)Wkh, (uint32_t*)Wkm,
        (uint32_t*)Wvh, (uint32_t*)Wvm, (uint32_t*)Wph, (uint32_t*)Wpm);
    // 1) activation splits
    split_act_kernel<<<(2 * Q4 + 255) / 256, 256>>>(
        (const float4*)q, (const float4*)v,
        (uint32_t*)qh, (uint32_t*)qm, (uint32_t*)vh, (uint32_t*)vm);

    const dim3 ggrd(EE / 128, MM / 128);   // (8, 64)

    // 2) qp = q @ Wq^T  -> planes
    gemm_bf_kernel<<<ggrd, 128, GEMM_SMEM>>>(qh, qm, Wqh, Wqm, nullptr, 0,
                                             (uint32_t*)qph, (uint32_t*)qpm, nullptr);
    // 3) kp = qp @ Wk^T (faithful quirk) -> planes
    gemm_bf_kernel<<<ggrd, 128, GEMM_SMEM>>>(qph, qpm, Wkh, Wkm, nullptr, 0,
                                             (uint32_t*)kph, (uint32_t*)kpm, nullptr);
    // 4) vp = v @ Wv^T  -> V^T planes
    gemm_bf_kernel<<<ggrd, 128, GEMM_SMEM>>>(vh, vm, Wvh, Wvm, nullptr, 1,
                                             (uint32_t*)vth, (uint32_t*)vtm, nullptr);
    // 5) causal flash attention (ncu capture lands here)
    attn_kernel<<<dim3(TT / 64, BB * HH), 128, ATTN_SMEM>>>(
        qph, qpm, kph, kpm, vth, vtm, (uint32_t*)yh, (uint32_t*)ym);
    // 6) out = y @ Wp^T + bp (f32)
    gemm_bf_kernel<<<ggrd, 128, GEMM_SMEM>>>(yh, ym, Wph, Wpm, bp, 2,
                                             nullptr, nullptr, out);
}